// round 5
// baseline (speedup 1.0000x reference)
#include <cuda_runtime.h>
#include <cuda_bf16.h>
#include <cuda_fp16.h>
#include <math.h>

// Problem constants
#define BDIM 64
#define TDIM 64
#define SDIM 128
#define HDIM 1024
#define EDIM 1024
#define VDIM 32000
#define G3H  3072          // 3*H
#define QGH  4096          // q(1024) | gh1(3072)

#define NBLK 148           // persistent grid: guaranteed co-resident (148 SM B300 / 152 SM GB300)
#define NTHR 256

typedef __nv_bfloat16 bf16;

// ---------------- scratch (static device globals; no allocation) ----------------
__device__ bf16  g_kprojb[(size_t)BDIM * SDIM * HDIM];   // [B,S,H] bf16
__device__ bf16  g_encYb [(size_t)BDIM * SDIM * HDIM];
__device__ bf16  g_xsb   [(size_t)TDIM * BDIM * EDIM];   // [T*B, E]
__device__ bf16  g_Wihxb [G3H * HDIM];                   // Wih0[:, H:2H]
__device__ bf16  g_Wih0cb[G3H * HDIM];                   // Wih0[:, 0:H]
__device__ bf16  g_Wih1b [G3H * HDIM];
__device__ bf16  g_Whh0b [G3H * HDIM];
__device__ bf16  g_Wcatb [QGH * HDIM];                   // [Wq; Whh1]
__device__ bf16  g_Wkb   [HDIM * HDIM];
__device__ bf16  g_Woutb [(size_t)VDIM * HDIM];
__device__ bf16  g_ysb   [(size_t)TDIM * BDIM * HDIM];
__device__ float g_Xg    [(size_t)TDIM * BDIM * G3H];    // x-part of gi0 (+bih0)
__device__ float g_bcat  [QGH];
__device__ float g_h     [2 * BDIM * HDIM];              // fp32 hidden
__device__ bf16  g_hb    [2 * BDIM * HDIM];              // bf16 mirror (GEMM A input)
__device__ float g_qgh1  [BDIM * QGH];                   // per-row: q | gh1
__device__ float g_attn  [BDIM * SDIM];
__device__ bf16  g_ctxb  [BDIM * HDIM];
__device__ float g_gh0   [BDIM * G3H];
__device__ float g_gi0   [BDIM * G3H];
__device__ float g_gi1   [BDIM * G3H];

// software grid barrier state (zero-init; invariant arrive == NBLK*release at kernel entry)
__device__ unsigned long long g_arrive;
__device__ unsigned long long g_release;

// ---------------- helpers ----------------
__device__ __forceinline__ float fast_tanh(float x) {
    float y; asm("tanh.approx.f32 %0, %1;" : "=f"(y) : "f"(x)); return y;
}
__device__ __forceinline__ float fast_sigmoid(float x) {
    return 1.0f / (1.0f + __expf(-x));
}
__device__ __forceinline__ float warpReduceSum(float v) {
    #pragma unroll
    for (int o = 16; o > 0; o >>= 1) v += __shfl_xor_sync(0xffffffffu, v, o);
    return v;
}
__device__ __forceinline__ float warpReduceMax(float v) {
    #pragma unroll
    for (int o = 16; o > 0; o >>= 1) v = fmaxf(v, __shfl_xor_sync(0xffffffffu, v, o));
    return v;
}

__device__ __forceinline__ void mma16816(float* d, const unsigned* a, const unsigned* b) {
    asm volatile(
        "mma.sync.aligned.m16n8k16.row.col.f32.bf16.bf16.f32 "
        "{%0,%1,%2,%3},{%4,%5,%6,%7},{%8,%9},{%0,%1,%2,%3};"
        : "+f"(d[0]), "+f"(d[1]), "+f"(d[2]), "+f"(d[3])
        : "r"(a[0]), "r"(a[1]), "r"(a[2]), "r"(a[3]), "r"(b[0]), "r"(b[1]));
}

#define CPASYNC16(dst_u32, src_ptr) \
    asm volatile("cp.async.cg.shared.global [%0], [%1], 16;" :: "r"(dst_u32), "l"(src_ptr))
#define CPCOMMIT() asm volatile("cp.async.commit_group;")
#define CPWAIT(n)  asm volatile("cp.async.wait_group %0;" :: "n"(n))

template <typename T> __device__ __forceinline__ T toOut(float v);
template <> __device__ __forceinline__ float toOut<float>(float v) { return v; }
template <> __device__ __forceinline__ bf16  toOut<bf16 >(float v) { return __float2bfloat16(v); }

// grid-wide epoch barrier (all NBLK blocks must be co-resident)
__device__ __forceinline__ void grid_sync() {
    __threadfence();
    __syncthreads();
    if (threadIdx.x == 0) {
        unsigned long long t = atomicAdd(&g_arrive, 1ULL) + 1ULL;
        unsigned long long target = (t + NBLK - 1) / NBLK;
        if ((t % NBLK) == 0ULL) {
            atomicAdd(&g_release, 1ULL);
        } else {
            unsigned long long r;
            do {
                asm volatile("ld.global.acquire.gpu.u64 %0, [%1];"
                             : "=l"(r) : "l"(&g_release));
                if (r < target) __nanosleep(64);
            } while (r < target);
        }
    }
    __syncthreads();
}

// ============ big bf16 tensor-core GEMM (cp.async double-buffered) ============
template <typename OutT, bool ROWMAP>
__global__ __launch_bounds__(256)
void mma_gemm(const bf16* __restrict__ A, const bf16* __restrict__ B,
              const float* __restrict__ bias, OutT* __restrict__ C,
              int M, int N, int K)
{
    constexpr int BM = 128, BN = 128, BK = 32, PAD = 8;
    __shared__ __align__(16) bf16 As[2][BM][BK + PAD];
    __shared__ __align__(16) bf16 Bs[2][BN][BK + PAD];

    const int bm = blockIdx.y * BM;
    const int bn = blockIdx.x * BN;
    const int tid = threadIdx.x;
    const int lane = tid & 31;
    const int warp = tid >> 5;
    const int wm = (warp >> 2) * 64;
    const int wn = (warp & 3) * 32;

    float acc[4][4][4];
    #pragma unroll
    for (int i = 0; i < 4; i++)
        #pragma unroll
        for (int j = 0; j < 4; j++)
            #pragma unroll
            for (int x = 0; x < 4; x++) acc[i][j][x] = 0.0f;

    const int r  = lane >> 2;
    const int c2 = (lane & 3) * 2;

    auto load_stage = [&](int s, int k0) {
        #pragma unroll
        for (int v = 0; v < 2; v++) {
            int idx = tid + v * 256;
            int row = idx >> 2;
            int c8  = (idx & 3) * 8;
            unsigned da = (unsigned)__cvta_generic_to_shared(&As[s][row][c8]);
            CPASYNC16(da, &A[(size_t)(bm + row) * K + k0 + c8]);
            unsigned db = (unsigned)__cvta_generic_to_shared(&Bs[s][row][c8]);
            CPASYNC16(db, &B[(size_t)(bn + row) * K + k0 + c8]);
        }
        CPCOMMIT();
    };

    const int NIT = K / BK;
    load_stage(0, 0);

    for (int it = 0; it < NIT; it++) {
        if (it + 1 < NIT) load_stage((it + 1) & 1, (it + 1) * BK);
        if (it + 1 < NIT) { CPWAIT(1); } else { CPWAIT(0); }
        __syncthreads();
        const int s = it & 1;

        #pragma unroll
        for (int ks = 0; ks < 2; ks++) {
            unsigned a[4][4], b[4][2];
            #pragma unroll
            for (int i = 0; i < 4; i++) {
                int mr = wm + i * 16;
                a[i][0] = *reinterpret_cast<const unsigned*>(&As[s][mr + r    ][ks * 16 + c2    ]);
                a[i][1] = *reinterpret_cast<const unsigned*>(&As[s][mr + r + 8][ks * 16 + c2    ]);
                a[i][2] = *reinterpret_cast<const unsigned*>(&As[s][mr + r    ][ks * 16 + c2 + 8]);
                a[i][3] = *reinterpret_cast<const unsigned*>(&As[s][mr + r + 8][ks * 16 + c2 + 8]);
            }
            #pragma unroll
            for (int j = 0; j < 4; j++) {
                int nr = wn + j * 8 + r;
                b[j][0] = *reinterpret_cast<const unsigned*>(&Bs[s][nr][ks * 16 + c2    ]);
                b[j][1] = *reinterpret_cast<const unsigned*>(&Bs[s][nr][ks * 16 + c2 + 8]);
            }
            #pragma unroll
            for (int i = 0; i < 4; i++)
                #pragma unroll
                for (int j = 0; j < 4; j++)
                    mma16816(acc[i][j], a[i], b[j]);
        }
        __syncthreads();
    }

    #pragma unroll
    for (int i = 0; i < 4; i++) {
        int grow0 = bm + wm + i * 16 + r;
        #pragma unroll
        for (int half = 0; half < 2; half++) {
            int g = grow0 + half * 8;
            size_t rowBase;
            if (ROWMAP) {
                int b_ = g & (BDIM - 1);
                int t_ = g >> 6;
                rowBase = (size_t)(b_ * TDIM + t_) * N;
            } else {
                rowBase = (size_t)g * N;
            }
            #pragma unroll
            for (int j = 0; j < 4; j++) {
                int col = bn + wn + j * 8 + c2;
                float b0 = bias ? bias[col]     : 0.0f;
                float b1 = bias ? bias[col + 1] : 0.0f;
                C[rowBase + col    ] = toOut<OutT>(acc[i][j][half * 2    ] + b0);
                C[rowBase + col + 1] = toOut<OutT>(acc[i][j][half * 2 + 1] + b1);
            }
        }
    }
}

// ============ 64x32 slab GEMM body for the persistent scan ============
// A[64,1024] bf16 (MUTABLE -> __ldcg), W[N,1024] bf16 (immutable), out fp32.
__device__ __forceinline__ void slab_gemm(
    const bf16* __restrict__ A, const bf16* __restrict__ W,
    const float* __restrict__ bias, const float* __restrict__ P, int ldp,
    float* __restrict__ C, int ldc, int bn,
    bf16 (*sA)[40], bf16 (*sW)[40])
{
    const int tid = threadIdx.x;
    const int lane = tid & 31;
    const int warp = tid >> 5;             // 8 warps: 4 (M) x 2 (N)
    const int wm = (warp >> 1) * 16;
    const int wn = (warp & 1) * 16;
    const int r  = lane >> 2;
    const int c2 = (lane & 3) * 2;

    float acc[2][4];
    #pragma unroll
    for (int j = 0; j < 2; j++)
        #pragma unroll
        for (int x = 0; x < 4; x++) acc[j][x] = 0.0f;

    const int arow = tid >> 2, ac8 = (tid & 3) * 8;
    for (int k0 = 0; k0 < HDIM; k0 += 32) {
        *reinterpret_cast<uint4*>(&sA[arow][ac8]) =
            __ldcg(reinterpret_cast<const uint4*>(&A[(size_t)arow * HDIM + k0 + ac8]));
        if (tid < 128) {
            *reinterpret_cast<uint4*>(&sW[arow][ac8]) =
                __ldg(reinterpret_cast<const uint4*>(&W[(size_t)(bn + arow) * HDIM + k0 + ac8]));
        }
        __syncthreads();

        #pragma unroll
        for (int ks = 0; ks < 2; ks++) {
            unsigned a[4], b[2][2];
            a[0] = *reinterpret_cast<const unsigned*>(&sA[wm + r    ][ks * 16 + c2    ]);
            a[1] = *reinterpret_cast<const unsigned*>(&sA[wm + r + 8][ks * 16 + c2    ]);
            a[2] = *reinterpret_cast<const unsigned*>(&sA[wm + r    ][ks * 16 + c2 + 8]);
            a[3] = *reinterpret_cast<const unsigned*>(&sA[wm + r + 8][ks * 16 + c2 + 8]);
            #pragma unroll
            for (int j = 0; j < 2; j++) {
                int nr = wn + j * 8 + r;
                b[j][0] = *reinterpret_cast<const unsigned*>(&sW[nr][ks * 16 + c2    ]);
                b[j][1] = *reinterpret_cast<const unsigned*>(&sW[nr][ks * 16 + c2 + 8]);
            }
            mma16816(acc[0], a, b[0]);
            mma16816(acc[1], a, b[1]);
        }
        __syncthreads();
    }

    #pragma unroll
    for (int j = 0; j < 2; j++) {
        #pragma unroll
        for (int half = 0; half < 2; half++) {
            int row = wm + r + half * 8;
            int col = bn + wn + j * 8 + c2;
            float v0 = acc[j][half * 2    ];
            float v1 = acc[j][half * 2 + 1];
            if (bias) { v0 += bias[col]; v1 += bias[col + 1]; }
            if (P)    { v0 += P[(size_t)row * ldp + col]; v1 += P[(size_t)row * ldp + col + 1]; }
            C[(size_t)row * ldc + col    ] = v0;
            C[(size_t)row * ldc + col + 1] = v1;
        }
    }
}

// ============ persistent scan kernel: all 64 steps, 7 phases/step ============
__global__ __launch_bounds__(NTHR)
void scan_kernel(const float* __restrict__ wv, const float* __restrict__ bv,
                 const float* __restrict__ bhh0, const float* __restrict__ bih1)
{
    __shared__ __align__(16) bf16 sA[64][40];
    __shared__ __align__(16) bf16 sW[32][40];
    __shared__ float sc[SDIM];
    __shared__ float red[8];

    const int tid = threadIdx.x;
    const int lane = tid & 31;
    const int warp = tid >> 5;
    const int blk = blockIdx.x;
    const float bv0 = bv[0];

    float* h0p = g_h;
    float* h1p = g_h + BDIM * HDIM;
    bf16*  h0b = g_hb;
    bf16*  h1b = g_hb + BDIM * HDIM;

    for (int t = 0; t < TDIM; t++) {
        // ---- P1: qgh1 = h1 @ Wcat^T + bcat (128 slabs); gh0 = h0 @ Whh0^T + bhh0 (96) ----
        for (int slab = blk; slab < 224; slab += NBLK) {
            if (slab < 128)
                slab_gemm(h1b, g_Wcatb, g_bcat, nullptr, 0,
                          g_qgh1, QGH, slab * 32, sA, sW);
            else
                slab_gemm(h0b, g_Whh0b, bhh0, nullptr, 0,
                          g_gh0, G3H, (slab - 128) * 32, sA, sW);
        }
        grid_sync();

        // ---- P2: scores[b,s] = wv . tanh(q[b] + kproj[b,s]) + bv  (warp per pair) ----
        {
            const float2* wv2 = reinterpret_cast<const float2*>(wv);
            for (int p = blk * 8 + warp; p < BDIM * SDIM; p += NBLK * 8) {
                const int b = p >> 7;
                const __nv_bfloat162* kp = reinterpret_cast<const __nv_bfloat162*>(
                    &g_kprojb[(size_t)p * HDIM]);
                const float2* q2 = reinterpret_cast<const float2*>(&g_qgh1[(size_t)b * QGH]);
                float sum = 0.0f;
                #pragma unroll 4
                for (int i = lane; i < HDIM / 2; i += 32) {
                    __nv_bfloat162 k = __ldg(&kp[i]);
                    float2 q = __ldcg(&q2[i]);
                    float2 w = __ldg(&wv2[i]);
                    __half2 hx = __floats2half2_rn(q.x + __low2float(k),
                                                   q.y + __high2float(k));
                    unsigned hin = *reinterpret_cast<unsigned*>(&hx);
                    unsigned hout;
                    asm("tanh.approx.f16x2 %0, %1;" : "=r"(hout) : "r"(hin));
                    __half2 ht = *reinterpret_cast<__half2*>(&hout);
                    float2 tv = __half22float2(ht);
                    sum += tv.x * w.x + tv.y * w.y;
                }
                sum = warpReduceSum(sum);
                if (lane == 0) g_attn[p] = sum + bv0;
            }
        }
        grid_sync();

        // ---- P3: softmax + ctx (blocks 0..127: b = blk>>1, h-half = blk&1) ----
        if (blk < 2 * BDIM) {
            const int b = blk >> 1;
            const int half = blk & 1;
            float v = (tid < SDIM) ? __ldcg(&g_attn[b * SDIM + tid]) : -1e30f;
            float m = warpReduceMax(v);
            if (lane == 0) red[warp] = m;
            __syncthreads();
            m = red[0];
            #pragma unroll
            for (int w = 1; w < 8; w++) m = fmaxf(m, red[w]);
            float e = (tid < SDIM) ? __expf(v - m) : 0.0f;
            float s = warpReduceSum(e);
            __syncthreads();
            if (lane == 0) red[warp] = s;
            __syncthreads();
            float tot = red[0];
            #pragma unroll
            for (int w = 1; w < 8; w++) tot += red[w];
            if (tid < SDIM) sc[tid] = e / tot;
            __syncthreads();

            const int h = half * 512 + tid * 2;
            const __nv_bfloat162* ey = reinterpret_cast<const __nv_bfloat162*>(
                &g_encYb[(size_t)b * SDIM * HDIM + h]);
            float a0 = 0.0f, a1 = 0.0f;
            #pragma unroll 8
            for (int s2 = 0; s2 < SDIM; s2++) {
                __nv_bfloat162 ev = __ldg(&ey[(size_t)s2 * (HDIM / 2)]);
                float w = sc[s2];
                a0 = fmaf(w, __low2float(ev),  a0);
                a1 = fmaf(w, __high2float(ev), a1);
            }
            *reinterpret_cast<__nv_bfloat162*>(&g_ctxb[b * HDIM + h]) =
                __floats2bfloat162_rn(a0, a1);
        }
        grid_sync();

        // ---- P4: gi0 = ctx @ Wih0c^T + Xg[t]  (96 slabs) ----
        for (int slab = blk; slab < 96; slab += NBLK)
            slab_gemm(g_ctxb, g_Wih0cb, nullptr,
                      g_Xg + (size_t)t * BDIM * G3H, G3H,
                      g_gi0, G3H, slab * 32, sA, sW);
        grid_sync();

        // ---- P5: gate0 -> h0, h0b ----
        for (int i = blk * NTHR + tid; i < BDIM * HDIM; i += NBLK * NTHR) {
            const int b = i >> 10;
            const int j = i & (HDIM - 1);
            const float* gib = g_gi0 + (size_t)b * G3H;
            const float* ghb = g_gh0 + (size_t)b * G3H;
            float r = fast_sigmoid(__ldcg(&gib[j]) + __ldcg(&ghb[j]));
            float z = fast_sigmoid(__ldcg(&gib[HDIM + j]) + __ldcg(&ghb[HDIM + j]));
            float n = fast_tanh(__ldcg(&gib[2 * HDIM + j]) + r * __ldcg(&ghb[2 * HDIM + j]));
            float hn = (1.0f - z) * n + z * __ldcg(&h0p[i]);
            h0p[i] = hn;
            h0b[i] = __float2bfloat16(hn);
        }
        grid_sync();

        // ---- P6: gi1 = h0_new @ Wih1^T + bih1  (96 slabs) ----
        for (int slab = blk; slab < 96; slab += NBLK)
            slab_gemm(h0b, g_Wih1b, bih1, nullptr, 0,
                      g_gi1, G3H, slab * 32, sA, sW);
        grid_sync();

        // ---- P7: gate1 -> h1, h1b, ys[t] ----
        for (int i = blk * NTHR + tid; i < BDIM * HDIM; i += NBLK * NTHR) {
            const int b = i >> 10;
            const int j = i & (HDIM - 1);
            const float* gib = g_gi1 + (size_t)b * G3H;
            const float* ghb = g_qgh1 + (size_t)b * QGH + HDIM;   // gh1 lives in qgh1[H:]
            float r = fast_sigmoid(__ldcg(&gib[j]) + __ldcg(&ghb[j]));
            float z = fast_sigmoid(__ldcg(&gib[HDIM + j]) + __ldcg(&ghb[HDIM + j]));
            float n = fast_tanh(__ldcg(&gib[2 * HDIM + j]) + r * __ldcg(&ghb[2 * HDIM + j]));
            float hn = (1.0f - z) * n + z * __ldcg(&h1p[i]);
            h1p[i] = hn;
            bf16 hb = __float2bfloat16(hn);
            h1b[i] = hb;
            g_ysb[(size_t)t * BDIM * HDIM + i] = hb;
        }
        grid_sync();
    }
}

// ---------------- embedding gather -> bf16 (one block per (t,b) row) ----------------
__global__ void gather_kernel(const int* __restrict__ X, const float* __restrict__ table)
{
    const int tb = blockIdx.x;                 // t*64+b
    const int b = tb & (BDIM - 1);
    const int t = tb >> 6;
    const float4* src = reinterpret_cast<const float4*>(
        &table[(size_t)X[b * TDIM + t] * EDIM]);
    float4 f = src[threadIdx.x];
    bf16* dst = &g_xsb[(size_t)tb * EDIM + threadIdx.x * 4];
    dst[0] = __float2bfloat16(f.x);
    dst[1] = __float2bfloat16(f.y);
    dst[2] = __float2bfloat16(f.z);
    dst[3] = __float2bfloat16(f.w);
}

// ---------------- vectorized fp32 -> bf16 ----------------
__global__ void f2bf4_kernel(const float* __restrict__ src, bf16* __restrict__ dst, size_t n4)
{
    size_t i = (size_t)blockIdx.x * blockDim.x + threadIdx.x;
    if (i >= n4) return;
    float4 f = reinterpret_cast<const float4*>(src)[i];
    reinterpret_cast<__nv_bfloat162*>(dst)[i * 2    ] = __floats2bfloat162_rn(f.x, f.y);
    reinterpret_cast<__nv_bfloat162*>(dst)[i * 2 + 1] = __floats2bfloat162_rn(f.z, f.w);
}
__global__ void f2bf4_strided_kernel(const float* __restrict__ src, int srcld, int srcoff,
                                     bf16* __restrict__ dst, int rows, int cols)
{
    size_t i = (size_t)blockIdx.x * blockDim.x + threadIdx.x;
    size_t n4 = (size_t)rows * cols / 4;
    if (i >= n4) return;
    int cpr = cols / 4;
    int r = (int)(i / cpr);
    int c4 = (int)(i % cpr);
    float4 f = *reinterpret_cast<const float4*>(&src[(size_t)r * srcld + srcoff + c4 * 4]);
    __nv_bfloat162* d = reinterpret_cast<__nv_bfloat162*>(&dst[(size_t)r * cols + c4 * 4]);
    d[0] = __floats2bfloat162_rn(f.x, f.y);
    d[1] = __floats2bfloat162_rn(f.z, f.w);
}

// ---------------- Wcat (bf16) / bcat build ----------------
__global__ void wcatb_kernel(const float* __restrict__ Wq, const float* __restrict__ Whh1)
{
    size_t i = (size_t)blockIdx.x * blockDim.x + threadIdx.x;
    size_t n4 = (size_t)QGH * HDIM / 4;
    if (i >= n4) return;
    size_t e = i * 4;
    int rr = (int)(e / HDIM);
    int c  = (int)(e % HDIM);
    const float* s = (rr < HDIM) ? &Wq[(size_t)rr * HDIM + c]
                                 : &Whh1[(size_t)(rr - HDIM) * HDIM + c];
    float4 f = *reinterpret_cast<const float4*>(s);
    __nv_bfloat162* d = reinterpret_cast<__nv_bfloat162*>(&g_Wcatb[e]);
    d[0] = __floats2bfloat162_rn(f.x, f.y);
    d[1] = __floats2bfloat162_rn(f.z, f.w);
}
__global__ void bcat_kernel(const float* __restrict__ bq, const float* __restrict__ bhh1)
{
    int i = blockIdx.x * blockDim.x + threadIdx.x;
    if (i >= QGH) return;
    g_bcat[i] = (i < HDIM) ? bq[i] : bhh1[i - HDIM];
}

// ---------------- init hidden: fp32 copy + bf16 mirror ----------------
__global__ void hinit_kernel(const float* __restrict__ h0in)
{
    int i = blockIdx.x * blockDim.x + threadIdx.x;
    if (i >= 2 * BDIM * HDIM) return;
    float v = h0in[i];
    g_h[i]  = v;
    g_hb[i] = __float2bfloat16(v);
}

// ---------------- in-place log-softmax over V (vectorized) ----------------
__global__ void logsoftmax_kernel(float* __restrict__ out)
{
    float4* p4 = reinterpret_cast<float4*>(out + (size_t)blockIdx.x * VDIM);
    const int n4 = VDIM / 4;
    const int tid = threadIdx.x;

    float m = -1e30f;
    for (int v = tid; v < n4; v += 256) {
        float4 f = p4[v];
        m = fmaxf(m, fmaxf(fmaxf(f.x, f.y), fmaxf(f.z, f.w)));
    }
    m = warpReduceMax(m);
    __shared__ float shm[8];
    if ((tid & 31) == 0) shm[tid >> 5] = m;
    __syncthreads();
    m = shm[0];
    #pragma unroll
    for (int w = 1; w < 8; w++) m = fmaxf(m, shm[w]);

    float s = 0.0f;
    for (int v = tid; v < n4; v += 256) {
        float4 f = p4[v];
        s += __expf(f.x - m) + __expf(f.y - m) + __expf(f.z - m) + __expf(f.w - m);
    }
    s = warpReduceSum(s);
    __shared__ float shs[8];
    if ((tid & 31) == 0) shs[tid >> 5] = s;
    __syncthreads();
    s = shs[0];
    #pragma unroll
    for (int w = 1; w < 8; w++) s += shs[w];

    const float lse = m + logf(s);
    for (int v = tid; v < n4; v += 256) {
        float4 f = p4[v];
        f.x -= lse; f.y -= lse; f.z -= lse; f.w -= lse;
        p4[v] = f;
    }
}

// ---------------- launcher ----------------
extern "C" void kernel_launch(void* const* d_in, const int* in_sizes, int n_in,
                              void* d_out, int out_size)
{
    (void)in_sizes; (void)n_in; (void)out_size;

    const int*   X     = (const int*)d_in[0];
    const float* encY  = (const float*)d_in[1];
    const float* h0in  = (const float*)d_in[2];
    const float* table = (const float*)d_in[3];
    const float* Wq    = (const float*)d_in[4];
    const float* bq    = (const float*)d_in[5];
    const float* Wk    = (const float*)d_in[6];
    const float* bk    = (const float*)d_in[7];
    const float* wv    = (const float*)d_in[8];
    const float* bv    = (const float*)d_in[9];
    const float* Wih0  = (const float*)d_in[10];
    const float* Whh0  = (const float*)d_in[11];
    const float* bih0  = (const float*)d_in[12];
    const float* bhh0  = (const float*)d_in[13];
    const float* Wih1  = (const float*)d_in[14];
    const float* Whh1  = (const float*)d_in[15];
    const float* bih1  = (const float*)d_in[16];
    const float* bhh1  = (const float*)d_in[17];
    const float* Wout  = (const float*)d_in[18];
    const float* bout  = (const float*)d_in[19];
    float* out = (float*)d_out;

    bf16 *kprojb, *encYb, *xsb, *Wihxb, *Wih0cb, *Wih1b, *Whh0b, *Woutb, *Wkb, *ysb;
    float *Xg;
    cudaGetSymbolAddress((void**)&kprojb, g_kprojb);
    cudaGetSymbolAddress((void**)&encYb,  g_encYb);
    cudaGetSymbolAddress((void**)&xsb,    g_xsb);
    cudaGetSymbolAddress((void**)&Wihxb,  g_Wihxb);
    cudaGetSymbolAddress((void**)&Wih0cb, g_Wih0cb);
    cudaGetSymbolAddress((void**)&Wih1b,  g_Wih1b);
    cudaGetSymbolAddress((void**)&Whh0b,  g_Whh0b);
    cudaGetSymbolAddress((void**)&Woutb,  g_Woutb);
    cudaGetSymbolAddress((void**)&Wkb,    g_Wkb);
    cudaGetSymbolAddress((void**)&ysb,    g_ysb);
    cudaGetSymbolAddress((void**)&Xg,     g_Xg);

    // ---- prologue: conversions ----
    gather_kernel<<<TDIM * BDIM, 256>>>(X, table);
    {
        size_t n4 = (size_t)BDIM * SDIM * HDIM / 4;
        f2bf4_kernel<<<(unsigned)((n4 + 255) / 256), 256>>>(encY, encYb, n4);
    }
    f2bf4_kernel<<<(HDIM * HDIM / 4 + 255) / 256, 256>>>(Wk, Wkb, (size_t)HDIM * HDIM / 4);
    {
        size_t n4 = (size_t)VDIM * HDIM / 4;
        f2bf4_kernel<<<(unsigned)((n4 + 255) / 256), 256>>>(Wout, Woutb, n4);
    }
    f2bf4_strided_kernel<<<(G3H * HDIM / 4 + 255) / 256, 256>>>(Wih0, 2 * HDIM, HDIM,
                                                                Wihxb, G3H, HDIM);
    f2bf4_strided_kernel<<<(G3H * HDIM / 4 + 255) / 256, 256>>>(Wih0, 2 * HDIM, 0,
                                                                Wih0cb, G3H, HDIM);
    f2bf4_kernel<<<(G3H * HDIM / 4 + 255) / 256, 256>>>(Whh0, Whh0b, (size_t)G3H * HDIM / 4);
    f2bf4_kernel<<<(G3H * HDIM / 4 + 255) / 256, 256>>>(Wih1, Wih1b, (size_t)G3H * HDIM / 4);
    wcatb_kernel<<<(QGH * HDIM / 4 + 255) / 256, 256>>>(Wq, Whh1);
    bcat_kernel<<<(QGH + 255) / 256, 256>>>(bq, bhh1);
    hinit_kernel<<<(2 * BDIM * HDIM + 255) / 256, 256>>>(h0in);

    // kproj (bf16 out), Xg (fp32, bih0 folded)
    mma_gemm<bf16, false><<<dim3(HDIM / 128, (BDIM * SDIM) / 128), 256>>>(
        encYb, Wkb, bk, kprojb, BDIM * SDIM, HDIM, HDIM);
    mma_gemm<float, false><<<dim3(G3H / 128, (TDIM * BDIM) / 128), 256>>>(
        xsb, Wihxb, bih0, Xg, TDIM * BDIM, G3H, HDIM);

    // ---- persistent recurrent scan (one launch, 64 steps) ----
    scan_kernel<<<NBLK, NTHR>>>(wv, bv, bhh0, bih1);

    // ---- logits (tensor core, ROWMAP into [B,T,V]) + log-softmax ----
    mma_gemm<float, true><<<dim3(VDIM / 128, (TDIM * BDIM) / 128), 256>>>(
        ysb, Woutb, bout, out, TDIM * BDIM, VDIM, HDIM);
    logsoftmax_kernel<<<BDIM * TDIM, 256>>>(out);
}

// round 6
// speedup vs baseline: 1.1316x; 1.1316x over previous
#include <cuda_runtime.h>
#include <cuda_bf16.h>
#include <cuda_fp16.h>
#include <math.h>

// Problem constants
#define BDIM 64
#define TDIM 64
#define SDIM 128
#define HDIM 1024
#define EDIM 1024
#define VDIM 32000
#define G3H  3072          // 3*H
#define QGH  4096          // q(1024) | gh1(3072)

typedef __nv_bfloat16 bf16;

// ---------------- scratch (static device globals; no allocation) ----------------
__device__ bf16  g_kprojb[(size_t)BDIM * SDIM * HDIM];   // [B,S,H] bf16
__device__ bf16  g_encYb [(size_t)BDIM * SDIM * HDIM];
__device__ bf16  g_xsb   [(size_t)TDIM * BDIM * EDIM];   // [T*B, E]
__device__ bf16  g_Wihxb [G3H * HDIM];                   // Wih0[:, H:2H]
__device__ bf16  g_Wih0cb[G3H * HDIM];                   // Wih0[:, 0:H]
__device__ bf16  g_Wih1b [G3H * HDIM];
__device__ bf16  g_Whh0b [G3H * HDIM];
__device__ bf16  g_Wcatb [QGH * HDIM];                   // [Wq; Whh1]
__device__ bf16  g_Wkb   [HDIM * HDIM];
__device__ bf16  g_Woutb [(size_t)VDIM * HDIM];
__device__ bf16  g_ysb   [(size_t)TDIM * BDIM * HDIM];
__device__ float g_Xg    [(size_t)TDIM * BDIM * G3H];    // x-part of gi0 (+bih0)
__device__ float g_bcat  [QGH];
__device__ float g_h     [2 * BDIM * HDIM];              // fp32 hidden
__device__ bf16  g_hb    [2 * BDIM * HDIM];              // bf16 mirror (GEMM A input)
__device__ float g_qgh1  [BDIM * QGH];                   // per-row: q | gh1
__device__ bf16  g_ctxb  [BDIM * HDIM];
__device__ float g_gh0   [BDIM * G3H];

// ---------------- helpers ----------------
__device__ __forceinline__ float fast_tanh(float x) {
    float y; asm("tanh.approx.f32 %0, %1;" : "=f"(y) : "f"(x)); return y;
}
__device__ __forceinline__ float fast_sigmoid(float x) {
    return 1.0f / (1.0f + __expf(-x));
}
__device__ __forceinline__ float warpReduceSum(float v) {
    #pragma unroll
    for (int o = 16; o > 0; o >>= 1) v += __shfl_xor_sync(0xffffffffu, v, o);
    return v;
}
__device__ __forceinline__ float warpReduceMax(float v) {
    #pragma unroll
    for (int o = 16; o > 0; o >>= 1) v = fmaxf(v, __shfl_xor_sync(0xffffffffu, v, o));
    return v;
}

__device__ __forceinline__ void mma16816(float* d, const unsigned* a, const unsigned* b) {
    asm volatile(
        "mma.sync.aligned.m16n8k16.row.col.f32.bf16.bf16.f32 "
        "{%0,%1,%2,%3},{%4,%5,%6,%7},{%8,%9},{%0,%1,%2,%3};"
        : "+f"(d[0]), "+f"(d[1]), "+f"(d[2]), "+f"(d[3])
        : "r"(a[0]), "r"(a[1]), "r"(a[2]), "r"(a[3]), "r"(b[0]), "r"(b[1]));
}

#define CPASYNC16(dst_u32, src_ptr) \
    asm volatile("cp.async.cg.shared.global [%0], [%1], 16;" :: "r"(dst_u32), "l"(src_ptr))
#define CPCOMMIT() asm volatile("cp.async.commit_group;")
#define CPWAIT(n)  asm volatile("cp.async.wait_group %0;" :: "n"(n))

template <typename T> __device__ __forceinline__ T toOut(float v);
template <> __device__ __forceinline__ float toOut<float>(float v) { return v; }
template <> __device__ __forceinline__ bf16  toOut<bf16 >(float v) { return __float2bfloat16(v); }

// ============ big bf16 tensor-core GEMM (cp.async double-buffered) ============
template <typename OutT, bool ROWMAP>
__global__ __launch_bounds__(256)
void mma_gemm(const bf16* __restrict__ A, const bf16* __restrict__ B,
              const float* __restrict__ bias, OutT* __restrict__ C,
              int M, int N, int K)
{
    constexpr int BM = 128, BN = 128, BK = 32, PAD = 8;
    __shared__ __align__(16) bf16 As[2][BM][BK + PAD];
    __shared__ __align__(16) bf16 Bs[2][BN][BK + PAD];

    const int bm = blockIdx.y * BM;
    const int bn = blockIdx.x * BN;
    const int tid = threadIdx.x;
    const int lane = tid & 31;
    const int warp = tid >> 5;
    const int wm = (warp >> 2) * 64;
    const int wn = (warp & 3) * 32;

    float acc[4][4][4];
    #pragma unroll
    for (int i = 0; i < 4; i++)
        #pragma unroll
        for (int j = 0; j < 4; j++)
            #pragma unroll
            for (int x = 0; x < 4; x++) acc[i][j][x] = 0.0f;

    const int r  = lane >> 2;
    const int c2 = (lane & 3) * 2;

    auto load_stage = [&](int s, int k0) {
        #pragma unroll
        for (int v = 0; v < 2; v++) {
            int idx = tid + v * 256;
            int row = idx >> 2;
            int c8  = (idx & 3) * 8;
            unsigned da = (unsigned)__cvta_generic_to_shared(&As[s][row][c8]);
            CPASYNC16(da, &A[(size_t)(bm + row) * K + k0 + c8]);
            unsigned db = (unsigned)__cvta_generic_to_shared(&Bs[s][row][c8]);
            CPASYNC16(db, &B[(size_t)(bn + row) * K + k0 + c8]);
        }
        CPCOMMIT();
    };

    const int NIT = K / BK;
    load_stage(0, 0);

    for (int it = 0; it < NIT; it++) {
        if (it + 1 < NIT) load_stage((it + 1) & 1, (it + 1) * BK);
        if (it + 1 < NIT) { CPWAIT(1); } else { CPWAIT(0); }
        __syncthreads();
        const int s = it & 1;

        #pragma unroll
        for (int ks = 0; ks < 2; ks++) {
            unsigned a[4][4], b[4][2];
            #pragma unroll
            for (int i = 0; i < 4; i++) {
                int mr = wm + i * 16;
                a[i][0] = *reinterpret_cast<const unsigned*>(&As[s][mr + r    ][ks * 16 + c2    ]);
                a[i][1] = *reinterpret_cast<const unsigned*>(&As[s][mr + r + 8][ks * 16 + c2    ]);
                a[i][2] = *reinterpret_cast<const unsigned*>(&As[s][mr + r    ][ks * 16 + c2 + 8]);
                a[i][3] = *reinterpret_cast<const unsigned*>(&As[s][mr + r + 8][ks * 16 + c2 + 8]);
            }
            #pragma unroll
            for (int j = 0; j < 4; j++) {
                int nr = wn + j * 8 + r;
                b[j][0] = *reinterpret_cast<const unsigned*>(&Bs[s][nr][ks * 16 + c2    ]);
                b[j][1] = *reinterpret_cast<const unsigned*>(&Bs[s][nr][ks * 16 + c2 + 8]);
            }
            #pragma unroll
            for (int i = 0; i < 4; i++)
                #pragma unroll
                for (int j = 0; j < 4; j++)
                    mma16816(acc[i][j], a[i], b[j]);
        }
        __syncthreads();
    }

    #pragma unroll
    for (int i = 0; i < 4; i++) {
        int grow0 = bm + wm + i * 16 + r;
        #pragma unroll
        for (int half = 0; half < 2; half++) {
            int g = grow0 + half * 8;
            size_t rowBase;
            if (ROWMAP) {
                int b_ = g & (BDIM - 1);
                int t_ = g >> 6;
                rowBase = (size_t)(b_ * TDIM + t_) * N;
            } else {
                rowBase = (size_t)g * N;
            }
            #pragma unroll
            for (int j = 0; j < 4; j++) {
                int col = bn + wn + j * 8 + c2;
                float b0 = bias ? bias[col]     : 0.0f;
                float b1 = bias ? bias[col + 1] : 0.0f;
                C[rowBase + col    ] = toOut<OutT>(acc[i][j][half * 2    ] + b0);
                C[rowBase + col + 1] = toOut<OutT>(acc[i][j][half * 2 + 1] + b1);
            }
        }
    }
}

// ============ 64x64 slab GEMM (cp.async double-buffered): one slab per block ============
// C[64, bn:bn+64] = A[64,1024] @ W[bn:bn+64, 1024]^T + bias
__device__ __forceinline__ void slab64_body(
    const bf16* __restrict__ A, const bf16* __restrict__ W,
    const float* __restrict__ bias, float* __restrict__ C, int ldc, int bn)
{
    constexpr int PAD = 8;
    __shared__ __align__(16) bf16 sA[2][64][32 + PAD];
    __shared__ __align__(16) bf16 sW[2][64][32 + PAD];

    const int tid = threadIdx.x;
    const int lane = tid & 31;
    const int warp = tid >> 5;           // 2 M-warps x 4 N-warps
    const int wm = (warp >> 2) * 32;
    const int wn = (warp & 3) * 16;
    const int r  = lane >> 2;
    const int c2 = (lane & 3) * 2;

    float acc[2][2][4];
    #pragma unroll
    for (int i = 0; i < 2; i++)
        #pragma unroll
        for (int j = 0; j < 2; j++)
            #pragma unroll
            for (int x = 0; x < 4; x++) acc[i][j][x] = 0.0f;

    const int lrow = tid >> 2;            // 0..63
    const int lc8  = (tid & 3) * 8;       // 0,8,16,24

    auto load_stage = [&](int s, int k0) {
        unsigned da = (unsigned)__cvta_generic_to_shared(&sA[s][lrow][lc8]);
        CPASYNC16(da, &A[(size_t)lrow * HDIM + k0 + lc8]);
        unsigned dw = (unsigned)__cvta_generic_to_shared(&sW[s][lrow][lc8]);
        CPASYNC16(dw, &W[(size_t)(bn + lrow) * HDIM + k0 + lc8]);
        CPCOMMIT();
    };

    load_stage(0, 0);
    for (int it = 0; it < 32; it++) {
        if (it + 1 < 32) { load_stage((it + 1) & 1, (it + 1) * 32); CPWAIT(1); }
        else             { CPWAIT(0); }
        __syncthreads();
        const int s = it & 1;
        #pragma unroll
        for (int ks = 0; ks < 2; ks++) {
            unsigned a[2][4], b[2][2];
            #pragma unroll
            for (int i = 0; i < 2; i++) {
                int mr = wm + i * 16;
                a[i][0] = *reinterpret_cast<const unsigned*>(&sA[s][mr + r    ][ks * 16 + c2    ]);
                a[i][1] = *reinterpret_cast<const unsigned*>(&sA[s][mr + r + 8][ks * 16 + c2    ]);
                a[i][2] = *reinterpret_cast<const unsigned*>(&sA[s][mr + r    ][ks * 16 + c2 + 8]);
                a[i][3] = *reinterpret_cast<const unsigned*>(&sA[s][mr + r + 8][ks * 16 + c2 + 8]);
            }
            #pragma unroll
            for (int j = 0; j < 2; j++) {
                int nr = wn + j * 8 + r;
                b[j][0] = *reinterpret_cast<const unsigned*>(&sW[s][nr][ks * 16 + c2    ]);
                b[j][1] = *reinterpret_cast<const unsigned*>(&sW[s][nr][ks * 16 + c2 + 8]);
            }
            #pragma unroll
            for (int i = 0; i < 2; i++)
                #pragma unroll
                for (int j = 0; j < 2; j++)
                    mma16816(acc[i][j], a[i], b[j]);
        }
        __syncthreads();
    }

    #pragma unroll
    for (int i = 0; i < 2; i++)
        #pragma unroll
        for (int half = 0; half < 2; half++) {
            int row = wm + i * 16 + half * 8 + r;
            #pragma unroll
            for (int j = 0; j < 2; j++) {
                int col = bn + wn + j * 8 + c2;
                float v0 = acc[i][j][half * 2    ];
                float v1 = acc[i][j][half * 2 + 1];
                if (bias) { v0 += bias[col]; v1 += bias[col + 1]; }
                C[(size_t)row * ldc + col    ] = v0;
                C[(size_t)row * ldc + col + 1] = v1;
            }
        }
}

// step-start: 112 blocks. slab<64: qgh1 = h1 @ Wcat^T + bcat; else gh0 = h0 @ Whh0^T + bhh0
__global__ __launch_bounds__(256)
void step_start_kernel(const float* __restrict__ bhh0)
{
    const bf16* h0b = g_hb;
    const bf16* h1b = g_hb + BDIM * HDIM;
    if (blockIdx.x < 64)
        slab64_body(h1b, g_Wcatb, g_bcat, g_qgh1, QGH, blockIdx.x * 64);
    else
        slab64_body(h0b, g_Whh0b, bhh0, g_gh0, G3H, (blockIdx.x - 64) * 64);
}

// ============ fused attention: scores + softmax + ctx, one block per b ============
__global__ __launch_bounds__(256)
void attn_fused_kernel(const float* __restrict__ wv, const float* __restrict__ bv)
{
    __shared__ float qs[HDIM];
    __shared__ float ws[HDIM];
    __shared__ float sc[SDIM];
    __shared__ float red[8];

    const int b = blockIdx.x;
    const int tid = threadIdx.x;
    const int lane = tid & 31;
    const int warp = tid >> 5;

    // load q and wv to shared (4 floats/thread)
    {
        float4 qf = *reinterpret_cast<const float4*>(&g_qgh1[(size_t)b * QGH + tid * 4]);
        *reinterpret_cast<float4*>(&qs[tid * 4]) = qf;
        float4 wf = *reinterpret_cast<const float4*>(&wv[tid * 4]);
        *reinterpret_cast<float4*>(&ws[tid * 4]) = wf;
    }
    __syncthreads();

    // scores: each warp computes 16 of the 128 s-rows
    #pragma unroll 1
    for (int si = 0; si < 16; si++) {
        const int s = warp * 16 + si;
        const __nv_bfloat162* kp = reinterpret_cast<const __nv_bfloat162*>(
            &g_kprojb[((size_t)b * SDIM + s) * HDIM]);
        float sum = 0.0f;
        #pragma unroll 4
        for (int i = lane; i < HDIM / 2; i += 32) {
            __nv_bfloat162 k = kp[i];
            __half2 hx = __floats2half2_rn(qs[i * 2]     + __low2float(k),
                                           qs[i * 2 + 1] + __high2float(k));
            unsigned hin = *reinterpret_cast<unsigned*>(&hx);
            unsigned hout;
            asm("tanh.approx.f16x2 %0, %1;" : "=r"(hout) : "r"(hin));
            __half2 ht = *reinterpret_cast<__half2*>(&hout);
            float2 tv = __half22float2(ht);
            sum += tv.x * ws[i * 2] + tv.y * ws[i * 2 + 1];
        }
        sum = warpReduceSum(sum);
        if (lane == 0) sc[s] = sum;
    }
    __syncthreads();

    // softmax over 128 (tid < 128 active; bv is constant shift, cancels but keep exact)
    {
        float v = (tid < SDIM) ? sc[tid] + bv[0] : -1e30f;
        float m = warpReduceMax(v);
        if (lane == 0) red[warp] = m;
        __syncthreads();
        m = red[0];
        #pragma unroll
        for (int w = 1; w < 8; w++) m = fmaxf(m, red[w]);
        float e = (tid < SDIM) ? __expf(v - m) : 0.0f;
        float s = warpReduceSum(e);
        __syncthreads();
        if (lane == 0) red[warp] = s;
        __syncthreads();
        float tot = red[0];
        #pragma unroll
        for (int w = 1; w < 8; w++) tot += red[w];
        __syncthreads();
        if (tid < SDIM) sc[tid] = e / tot;
    }
    __syncthreads();

    // ctx: thread handles 4 h-columns
    {
        const int c0 = tid * 4;
        const bf16* ey = &g_encYb[(size_t)b * SDIM * HDIM + c0];
        float a0 = 0.0f, a1 = 0.0f, a2 = 0.0f, a3 = 0.0f;
        #pragma unroll 4
        for (int s = 0; s < SDIM; s++) {
            uint2 u = *reinterpret_cast<const uint2*>(&ey[(size_t)s * HDIM]);
            __nv_bfloat162 p0 = *reinterpret_cast<__nv_bfloat162*>(&u.x);
            __nv_bfloat162 p1 = *reinterpret_cast<__nv_bfloat162*>(&u.y);
            float w = sc[s];
            a0 = fmaf(w, __low2float(p0),  a0);
            a1 = fmaf(w, __high2float(p0), a1);
            a2 = fmaf(w, __low2float(p1),  a2);
            a3 = fmaf(w, __high2float(p1), a3);
        }
        __nv_bfloat162* d = reinterpret_cast<__nv_bfloat162*>(&g_ctxb[b * HDIM + c0]);
        d[0] = __floats2bfloat162_rn(a0, a1);
        d[1] = __floats2bfloat162_rn(a2, a3);
    }
}

// ============ fused GRU: gi GEMM (3 gate slabs, shared A) + in-register gate ============
// 32 blocks; block bn = blk*32 covers j-columns [bn, bn+32).
// gi[part] = A @ W[part*H + bn : .. +32, :]^T (+ bias[part*H+col]) (+ Xgt[row, part*H+col])
// then r,z,n gate against GH[row*ldgh + part*H + col] and h[row*H+col].
__global__ __launch_bounds__(256)
void gru_fused_kernel(const bf16* __restrict__ A, const bf16* __restrict__ W,
                      const float* __restrict__ bias, const float* __restrict__ Xgt,
                      const float* __restrict__ GH, int ldgh,
                      float* __restrict__ h, bf16* __restrict__ hb,
                      bf16* __restrict__ ys)
{
    constexpr int PAD = 8;
    __shared__ __align__(16) bf16 sA[2][64][32 + PAD];
    __shared__ __align__(16) bf16 sW[2][3][32][32 + PAD];

    const int tid = threadIdx.x;
    const int lane = tid & 31;
    const int warp = tid >> 5;            // 4 M-warps x 2 N-warps
    const int wm = (warp >> 1) * 16;
    const int wn = (warp & 1) * 16;
    const int r  = lane >> 2;
    const int c2 = (lane & 3) * 2;
    const int bn = blockIdx.x * 32;

    float acc[3][2][4];
    #pragma unroll
    for (int g = 0; g < 3; g++)
        #pragma unroll
        for (int j = 0; j < 2; j++)
            #pragma unroll
            for (int x = 0; x < 4; x++) acc[g][j][x] = 0.0f;

    const int arow = tid >> 2, ac8 = (tid & 3) * 8;

    auto load_stage = [&](int s, int k0) {
        unsigned da = (unsigned)__cvta_generic_to_shared(&sA[s][arow][ac8]);
        CPASYNC16(da, &A[(size_t)arow * HDIM + k0 + ac8]);
        // W: 3 x 32 rows x 32 cols = 384 x 16B chunks
        {
            int idx = tid;                 // 0..255
            int part = idx >> 7;           // 0..1
            int row  = (idx >> 2) & 31;
            int c8   = (idx & 3) * 8;
            unsigned dw = (unsigned)__cvta_generic_to_shared(&sW[s][part][row][c8]);
            CPASYNC16(dw, &W[(size_t)(part * HDIM + bn + row) * HDIM + k0 + c8]);
        }
        if (tid < 128) {
            int idx = tid + 256;           // 256..383 -> part 2
            int part = idx >> 7;
            int row  = (idx >> 2) & 31;
            int c8   = (idx & 3) * 8;
            unsigned dw = (unsigned)__cvta_generic_to_shared(&sW[s][part][row][c8]);
            CPASYNC16(dw, &W[(size_t)(part * HDIM + bn + row) * HDIM + k0 + c8]);
        }
        CPCOMMIT();
    };

    load_stage(0, 0);
    for (int it = 0; it < 32; it++) {
        if (it + 1 < 32) { load_stage((it + 1) & 1, (it + 1) * 32); CPWAIT(1); }
        else             { CPWAIT(0); }
        __syncthreads();
        const int s = it & 1;
        #pragma unroll
        for (int ks = 0; ks < 2; ks++) {
            unsigned a[4];
            a[0] = *reinterpret_cast<const unsigned*>(&sA[s][wm + r    ][ks * 16 + c2    ]);
            a[1] = *reinterpret_cast<const unsigned*>(&sA[s][wm + r + 8][ks * 16 + c2    ]);
            a[2] = *reinterpret_cast<const unsigned*>(&sA[s][wm + r    ][ks * 16 + c2 + 8]);
            a[3] = *reinterpret_cast<const unsigned*>(&sA[s][wm + r + 8][ks * 16 + c2 + 8]);
            #pragma unroll
            for (int g = 0; g < 3; g++) {
                unsigned b0[2], b1[2];
                int nr0 = wn + r;
                int nr1 = wn + 8 + r;
                b0[0] = *reinterpret_cast<const unsigned*>(&sW[s][g][nr0][ks * 16 + c2    ]);
                b0[1] = *reinterpret_cast<const unsigned*>(&sW[s][g][nr0][ks * 16 + c2 + 8]);
                b1[0] = *reinterpret_cast<const unsigned*>(&sW[s][g][nr1][ks * 16 + c2    ]);
                b1[1] = *reinterpret_cast<const unsigned*>(&sW[s][g][nr1][ks * 16 + c2 + 8]);
                mma16816(acc[g][0], a, b0);
                mma16816(acc[g][1], a, b1);
            }
        }
        __syncthreads();
    }

    // in-register GRU gate on the 8 (row,col) positions this thread owns
    #pragma unroll
    for (int j = 0; j < 2; j++) {
        #pragma unroll
        for (int half = 0; half < 2; half++) {
            int row = wm + half * 8 + r;            // b index (0..63)
            #pragma unroll
            for (int e = 0; e < 2; e++) {
                int col = bn + wn + j * 8 + c2 + e; // j index (0..1023)
                float gr = acc[0][j][half * 2 + e];
                float gz = acc[1][j][half * 2 + e];
                float gn = acc[2][j][half * 2 + e];
                if (bias) {
                    gr += bias[col];
                    gz += bias[HDIM + col];
                    gn += bias[2 * HDIM + col];
                }
                if (Xgt) {
                    const float* xr = &Xgt[(size_t)row * G3H + col];
                    gr += xr[0];
                    gz += xr[HDIM];
                    gn += xr[2 * HDIM];
                }
                const float* ghp = &GH[(size_t)row * ldgh + col];
                float rr = fast_sigmoid(gr + ghp[0]);
                float zz = fast_sigmoid(gz + ghp[HDIM]);
                float nn = fast_tanh(gn + rr * ghp[2 * HDIM]);
                int hi = row * HDIM + col;
                float hn = (1.0f - zz) * nn + zz * h[hi];
                h[hi]  = hn;
                bf16 hv = __float2bfloat16(hn);
                hb[hi] = hv;
                if (ys) ys[hi] = hv;
            }
        }
    }
}

// ---------------- embedding gather -> bf16 (one block per (t,b) row) ----------------
__global__ void gather_kernel(const int* __restrict__ X, const float* __restrict__ table)
{
    const int tb = blockIdx.x;                 // t*64+b
    const int b = tb & (BDIM - 1);
    const int t = tb >> 6;
    const float4* src = reinterpret_cast<const float4*>(
        &table[(size_t)X[b * TDIM + t] * EDIM]);
    float4 f = src[threadIdx.x];
    bf16* dst = &g_xsb[(size_t)tb * EDIM + threadIdx.x * 4];
    dst[0] = __float2bfloat16(f.x);
    dst[1] = __float2bfloat16(f.y);
    dst[2] = __float2bfloat16(f.z);
    dst[3] = __float2bfloat16(f.w);
}

// ---------------- vectorized fp32 -> bf16 ----------------
__global__ void f2bf4_kernel(const float* __restrict__ src, bf16* __restrict__ dst, size_t n4)
{
    size_t i = (size_t)blockIdx.x * blockDim.x + threadIdx.x;
    if (i >= n4) return;
    float4 f = reinterpret_cast<const float4*>(src)[i];
    reinterpret_cast<__nv_bfloat162*>(dst)[i * 2    ] = __floats2bfloat162_rn(f.x, f.y);
    reinterpret_cast<__nv_bfloat162*>(dst)[i * 2 + 1] = __floats2bfloat162_rn(f.z, f.w);
}
__global__ void f2bf4_strided_kernel(const float* __restrict__ src, int srcld, int srcoff,
                                     bf16* __restrict__ dst, int rows, int cols)
{
    size_t i = (size_t)blockIdx.x * blockDim.x + threadIdx.x;
    size_t n4 = (size_t)rows * cols / 4;
    if (i >= n4) return;
    int cpr = cols / 4;
    int r = (int)(i / cpr);
    int c4 = (int)(i % cpr);
    float4 f = *reinterpret_cast<const float4*>(&src[(size_t)r * srcld + srcoff + c4 * 4]);
    __nv_bfloat162* d = reinterpret_cast<__nv_bfloat162*>(&dst[(size_t)r * cols + c4 * 4]);
    d[0] = __floats2bfloat162_rn(f.x, f.y);
    d[1] = __floats2bfloat162_rn(f.z, f.w);
}

// ---------------- Wcat (bf16) / bcat build ----------------
__global__ void wcatb_kernel(const float* __restrict__ Wq, const float* __restrict__ Whh1)
{
    size_t i = (size_t)blockIdx.x * blockDim.x + threadIdx.x;
    size_t n4 = (size_t)QGH * HDIM / 4;
    if (i >= n4) return;
    size_t e = i * 4;
    int rr = (int)(e / HDIM);
    int c  = (int)(e % HDIM);
    const float* s = (rr < HDIM) ? &Wq[(size_t)rr * HDIM + c]
                                 : &Whh1[(size_t)(rr - HDIM) * HDIM + c];
    float4 f = *reinterpret_cast<const float4*>(s);
    __nv_bfloat162* d = reinterpret_cast<__nv_bfloat162*>(&g_Wcatb[e]);
    d[0] = __floats2bfloat162_rn(f.x, f.y);
    d[1] = __floats2bfloat162_rn(f.z, f.w);
}
__global__ void bcat_kernel(const float* __restrict__ bq, const float* __restrict__ bhh1)
{
    int i = blockIdx.x * blockDim.x + threadIdx.x;
    if (i >= QGH) return;
    g_bcat[i] = (i < HDIM) ? bq[i] : bhh1[i - HDIM];
}

// ---------------- init hidden: fp32 copy + bf16 mirror ----------------
__global__ void hinit_kernel(const float* __restrict__ h0in)
{
    int i = blockIdx.x * blockDim.x + threadIdx.x;
    if (i >= 2 * BDIM * HDIM) return;
    float v = h0in[i];
    g_h[i]  = v;
    g_hb[i] = __float2bfloat16(v);
}

// ---------------- in-place log-softmax over V (vectorized) ----------------
__global__ void logsoftmax_kernel(float* __restrict__ out)
{
    float4* p4 = reinterpret_cast<float4*>(out + (size_t)blockIdx.x * VDIM);
    const int n4 = VDIM / 4;
    const int tid = threadIdx.x;

    float m = -1e30f;
    for (int v = tid; v < n4; v += 256) {
        float4 f = p4[v];
        m = fmaxf(m, fmaxf(fmaxf(f.x, f.y), fmaxf(f.z, f.w)));
    }
    m = warpReduceMax(m);
    __shared__ float shm[8];
    if ((tid & 31) == 0) shm[tid >> 5] = m;
    __syncthreads();
    m = shm[0];
    #pragma unroll
    for (int w = 1; w < 8; w++) m = fmaxf(m, shm[w]);

    float s = 0.0f;
    for (int v = tid; v < n4; v += 256) {
        float4 f = p4[v];
        s += __expf(f.x - m) + __expf(f.y - m) + __expf(f.z - m) + __expf(f.w - m);
    }
    s = warpReduceSum(s);
    __shared__ float shs[8];
    if ((tid & 31) == 0) shs[tid >> 5] = s;
    __syncthreads();
    s = shs[0];
    #pragma unroll
    for (int w = 1; w < 8; w++) s += shs[w];

    const float lse = m + logf(s);
    for (int v = tid; v < n4; v += 256) {
        float4 f = p4[v];
        f.x -= lse; f.y -= lse; f.z -= lse; f.w -= lse;
        p4[v] = f;
    }
}

// ---------------- launcher ----------------
extern "C" void kernel_launch(void* const* d_in, const int* in_sizes, int n_in,
                              void* d_out, int out_size)
{
    (void)in_sizes; (void)n_in; (void)out_size;

    const int*   X     = (const int*)d_in[0];
    const float* encY  = (const float*)d_in[1];
    const float* h0in  = (const float*)d_in[2];
    const float* table = (const float*)d_in[3];
    const float* Wq    = (const float*)d_in[4];
    const float* bq    = (const float*)d_in[5];
    const float* Wk    = (const float*)d_in[6];
    const float* bk    = (const float*)d_in[7];
    const float* wv    = (const float*)d_in[8];
    const float* bv    = (const float*)d_in[9];
    const float* Wih0  = (const float*)d_in[10];
    const float* Whh0  = (const float*)d_in[11];
    const float* bih0  = (const float*)d_in[12];
    const float* bhh0  = (const float*)d_in[13];
    const float* Wih1  = (const float*)d_in[14];
    const float* Whh1  = (const float*)d_in[15];
    const float* bih1  = (const float*)d_in[16];
    const float* bhh1  = (const float*)d_in[17];
    const float* Wout  = (const float*)d_in[18];
    const float* bout  = (const float*)d_in[19];
    float* out = (float*)d_out;

    bf16 *kprojb, *encYb, *xsb, *Wihxb, *Wih0cb, *Wih1b, *Whh0b, *Woutb, *Wkb, *ysb, *hb, *ctxb;
    float *Xg, *h, *gh0, *qgh1;
    cudaGetSymbolAddress((void**)&kprojb, g_kprojb);
    cudaGetSymbolAddress((void**)&encYb,  g_encYb);
    cudaGetSymbolAddress((void**)&xsb,    g_xsb);
    cudaGetSymbolAddress((void**)&Wihxb,  g_Wihxb);
    cudaGetSymbolAddress((void**)&Wih0cb, g_Wih0cb);
    cudaGetSymbolAddress((void**)&Wih1b,  g_Wih1b);
    cudaGetSymbolAddress((void**)&Whh0b,  g_Whh0b);
    cudaGetSymbolAddress((void**)&Woutb,  g_Woutb);
    cudaGetSymbolAddress((void**)&Wkb,    g_Wkb);
    cudaGetSymbolAddress((void**)&ysb,    g_ysb);
    cudaGetSymbolAddress((void**)&hb,     g_hb);
    cudaGetSymbolAddress((void**)&ctxb,   g_ctxb);
    cudaGetSymbolAddress((void**)&Xg,     g_Xg);
    cudaGetSymbolAddress((void**)&h,      g_h);
    cudaGetSymbolAddress((void**)&gh0,    g_gh0);
    cudaGetSymbolAddress((void**)&qgh1,   g_qgh1);

    // ---- prologue: conversions ----
    gather_kernel<<<TDIM * BDIM, 256>>>(X, table);
    {
        size_t n4 = (size_t)BDIM * SDIM * HDIM / 4;
        f2bf4_kernel<<<(unsigned)((n4 + 255) / 256), 256>>>(encY, encYb, n4);
    }
    f2bf4_kernel<<<(HDIM * HDIM / 4 + 255) / 256, 256>>>(Wk, Wkb, (size_t)HDIM * HDIM / 4);
    {
        size_t n4 = (size_t)VDIM * HDIM / 4;
        f2bf4_kernel<<<(unsigned)((n4 + 255) / 256), 256>>>(Wout, Woutb, n4);
    }
    f2bf4_strided_kernel<<<(G3H * HDIM / 4 + 255) / 256, 256>>>(Wih0, 2 * HDIM, HDIM,
                                                                Wihxb, G3H, HDIM);
    f2bf4_strided_kernel<<<(G3H * HDIM / 4 + 255) / 256, 256>>>(Wih0, 2 * HDIM, 0,
                                                                Wih0cb, G3H, HDIM);
    f2bf4_kernel<<<(G3H * HDIM / 4 + 255) / 256, 256>>>(Whh0, Whh0b, (size_t)G3H * HDIM / 4);
    f2bf4_kernel<<<(G3H * HDIM / 4 + 255) / 256, 256>>>(Wih1, Wih1b, (size_t)G3H * HDIM / 4);
    wcatb_kernel<<<(QGH * HDIM / 4 + 255) / 256, 256>>>(Wq, Whh1);
    bcat_kernel<<<(QGH + 255) / 256, 256>>>(bq, bhh1);
    hinit_kernel<<<(2 * BDIM * HDIM + 255) / 256, 256>>>(h0in);

    // kproj (bf16 out), Xg (fp32, bih0 folded)
    mma_gemm<bf16, false><<<dim3(HDIM / 128, (BDIM * SDIM) / 128), 256>>>(
        encYb, Wkb, bk, kprojb, BDIM * SDIM, HDIM, HDIM);
    mma_gemm<float, false><<<dim3(G3H / 128, (TDIM * BDIM) / 128), 256>>>(
        xsb, Wihxb, bih0, Xg, TDIM * BDIM, G3H, HDIM);

    bf16* h0b = hb;
    bf16* h1b = hb + BDIM * HDIM;
    float* h0p = h;
    float* h1p = h + BDIM * HDIM;

    // ---- recurrent scan: 4 launches per step ----
    for (int t = 0; t < TDIM; t++) {
        step_start_kernel<<<112, 256>>>(bhh0);
        attn_fused_kernel<<<BDIM, 256>>>(wv, bv);
        // gi0 + gate0 -> h0, h0b
        gru_fused_kernel<<<32, 256>>>(ctxb, Wih0cb, nullptr,
                                      Xg + (size_t)t * BDIM * G3H,
                                      gh0, G3H, h0p, h0b, nullptr);
        // gi1 + gate1 -> h1, h1b, ys[t]   (gh1 lives at qgh1[:, H:])
        gru_fused_kernel<<<32, 256>>>(h0b, Wih1b, bih1, nullptr,
                                      qgh1 + HDIM, QGH, h1p, h1b,
                                      ysb + (size_t)t * BDIM * HDIM);
    }

    // ---- logits (tensor core, ROWMAP into [B,T,V]) + log-softmax ----
    mma_gemm<float, true><<<dim3(VDIM / 128, (TDIM * BDIM) / 128), 256>>>(
        ysb, Woutb, bout, out, TDIM * BDIM, VDIM, HDIM);
    logsoftmax_kernel<<<BDIM * TDIM, 256>>>(out);
}